// round 13
// baseline (speedup 1.0000x reference)
#include <cuda_runtime.h>
#include <cuda_bf16.h>
#include <math.h>
#include <stdint.h>

#define TT 512
#define BB 128
#define DIN 512
#define HD 512
#define NR 2048
#define MTOT (TT * BB)          // 65536
#define OUTBASE ((size_t)TT * BB * HD)

// ---------------- scratch ----------------
__device__ __nv_bfloat16 g_Xhi[(size_t)MTOT * DIN];
__device__ __nv_bfloat16 g_Xlo[(size_t)MTOT * DIN];
__device__ __nv_bfloat16 g_Whi[NR * DIN];        // x-part weights hi
__device__ __nv_bfloat16 g_Wlo[NR * DIN];        // x-part weights lo
__device__ __nv_bfloat16 g_Rhi[NR * HD];         // h-part weights hi
__device__ __nv_bfloat16 g_Rlo[NR * HD];         // h-part weights lo
__device__ float g_bias[NR];
__device__ float g_xproj[(size_t)NR * MTOT];     // [r][m]
__device__ __nv_bfloat16 g_hbhi[4][BB * HD];     // h hi, [b][k], 4-slot ring
__device__ __nv_bfloat16 g_hblo[4][BB * HD];     // h lo
__device__ unsigned g_pflag[4][32];              // [bg][rowg] monotonic step flags

// ---------------- PTX helpers (sm_80-compatible ISA only) ----------------
__device__ __forceinline__ uint32_t smem_u32(const void* p) {
    uint32_t a;
    asm("{ .reg .u64 t; cvta.to.shared.u64 t, %1; cvt.u32.u64 %0, t; }" : "=r"(a) : "l"(p));
    return a;
}

__device__ __forceinline__ void ldsm4(uint32_t& r0, uint32_t& r1, uint32_t& r2, uint32_t& r3,
                                      uint32_t addr) {
    asm volatile("ldmatrix.sync.aligned.m8n8.x4.shared.b16 {%0,%1,%2,%3}, [%4];"
                 : "=r"(r0), "=r"(r1), "=r"(r2), "=r"(r3) : "r"(addr));
}

__device__ __forceinline__ void mma16816(float* c, const uint32_t* a, const uint32_t* b) {
    asm volatile("mma.sync.aligned.m16n8k16.row.col.f32.bf16.bf16.f32 "
                 "{%0,%1,%2,%3}, {%4,%5,%6,%7}, {%8,%9}, {%0,%1,%2,%3};"
                 : "+f"(c[0]), "+f"(c[1]), "+f"(c[2]), "+f"(c[3])
                 : "r"(a[0]), "r"(a[1]), "r"(a[2]), "r"(a[3]), "r"(b[0]), "r"(b[1]));
}

__device__ __forceinline__ void cpasync16(uint32_t saddr, const void* g) {
    asm volatile("cp.async.cg.shared.global [%0], [%1], 16;" :: "r"(saddr), "l"(g));
}
#define CP_COMMIT() asm volatile("cp.async.commit_group;" ::: "memory")
#define CP_WAIT0()  asm volatile("cp.async.wait_group 0;" ::: "memory")

__device__ __forceinline__ unsigned ld_acq(const unsigned* p) {
    unsigned v;
    asm volatile("ld.acquire.gpu.global.u32 %0, [%1];" : "=r"(v) : "l"(p) : "memory");
    return v;
}
__device__ __forceinline__ void st_rel(unsigned* p, unsigned v) {
    asm volatile("st.release.gpu.global.u32 [%0], %1;" :: "l"(p), "r"(v) : "memory");
}

// ---------------- pack weights (bf16 hi/lo both halves), zero h0 ----------------
__global__ void pack_kernel(const float* __restrict__ Wf, const float* __restrict__ Wi,
                            const float* __restrict__ Wg_, const float* __restrict__ Wo,
                            const float* __restrict__ bf, const float* __restrict__ bi,
                            const float* __restrict__ bg, const float* __restrict__ bo) {
    int idx = blockIdx.x * blockDim.x + threadIdx.x;
    if (idx < NR * DIN) {
        int r = idx >> 9;
        int k = idx & 511;
        int gate = r >> 9;
        int j = r & 511;
        const float* W = (gate == 0) ? Wf : (gate == 1) ? Wi : (gate == 2) ? Wg_ : Wo;
        float wx = W[j * 1024 + k];
        __nv_bfloat16 hi = __float2bfloat16(wx);
        g_Whi[idx] = hi;
        g_Wlo[idx] = __float2bfloat16(wx - __bfloat162float(hi));
        float wh = W[j * 1024 + 512 + k];
        __nv_bfloat16 rh = __float2bfloat16(wh);
        g_Rhi[idx] = rh;
        g_Rlo[idx] = __float2bfloat16(wh - __bfloat162float(rh));
        if (k == 0) {
            const float* bb = (gate == 0) ? bf : (gate == 1) ? bi : (gate == 2) ? bg : bo;
            g_bias[r] = bb[j];
        }
    }
    if (idx < BB * HD) {
        g_hbhi[0][idx] = __float2bfloat16(0.f);
        g_hblo[0][idx] = __float2bfloat16(0.f);
    }
}

// ---------------- split X into bf16 hi/lo ----------------
__global__ void split_x(const float* __restrict__ X) {
    size_t i = (size_t)blockIdx.x * blockDim.x + threadIdx.x;  // float4 index
    if (i < (size_t)MTOT * DIN / 4) {
        float4 v = __ldg((const float4*)X + i);
        __nv_bfloat16 h0 = __float2bfloat16(v.x), h1 = __float2bfloat16(v.y);
        __nv_bfloat16 h2 = __float2bfloat16(v.z), h3 = __float2bfloat16(v.w);
        __nv_bfloat162* ph = (__nv_bfloat162*)g_Xhi;
        __nv_bfloat162* pl = (__nv_bfloat162*)g_Xlo;
        ph[i * 2] = __nv_bfloat162(h0, h1);
        ph[i * 2 + 1] = __nv_bfloat162(h2, h3);
        pl[i * 2] = __nv_bfloat162(__float2bfloat16(v.x - __bfloat162float(h0)),
                                   __float2bfloat16(v.y - __bfloat162float(h1)));
        pl[i * 2 + 1] = __nv_bfloat162(__float2bfloat16(v.z - __bfloat162float(h2)),
                                       __float2bfloat16(v.w - __bfloat162float(h3)));
    }
}

// ---------------- xproj via mma.sync (proven in R8) ----------------
__global__ void __launch_bounds__(256) xproj_mma(int dummy) {
    extern __shared__ char smraw[];
    char* smp = (char*)(((uintptr_t)smraw + 127) & ~(uintptr_t)127);
    uint32_t ub = smem_u32(smp);
    int tid = threadIdx.x, wid = tid >> 5, lane = tid & 31;
    int wr = wid & 1, wm = wid >> 1;
    int r0 = blockIdx.y * 128, m0 = blockIdx.x * 128;

    float acc[4][4][4];
#pragma unroll
    for (int f = 0; f < 4; f++)
#pragma unroll
        for (int mf = 0; mf < 4; mf++)
#pragma unroll
            for (int q = 0; q < 4; q++) acc[f][mf][q] = 0.f;

    const __nv_bfloat16* srcs[4] = {
        g_Whi + (size_t)r0 * DIN, g_Wlo + (size_t)r0 * DIN,
        g_Xhi + (size_t)m0 * DIN, g_Xlo + (size_t)m0 * DIN };

    for (int kc = 0; kc < 8; kc++) {
        __syncthreads();
#pragma unroll
        for (int mat = 0; mat < 4; mat++) {
            const float4* src = (const float4*)srcs[mat];
            char* dst = smp + mat * 16384;
#pragma unroll
            for (int it = 0; it < 4; it++) {
                int idx = tid + it * 256;
                int row = idx & 127;
                int kt8 = idx >> 7;
                uint32_t off = (uint32_t)(((row >> 3) * 8 + kt8) * 128 + (row & 7) * 16);
                *(float4*)(dst + off) = __ldg(src + (size_t)row * 64 + kc * 8 + kt8);
            }
        }
        __syncthreads();
        uint32_t aH = ub, aL = ub + 16384, bH = ub + 32768, bL = ub + 49152;
#pragma unroll
        for (int kk = 0; kk < 4; kk++) {
            uint32_t aoff[4], boff[2];
#pragma unroll
            for (int f = 0; f < 4; f++)
                aoff[f] = (uint32_t)(((wr * 8 + f * 2 + ((lane >> 3) & 1)) * 8
                                      + (2 * kk + (lane >> 4))) * 128 + (lane & 7) * 16);
#pragma unroll
            for (int p = 0; p < 2; p++)
                boff[p] = (uint32_t)(((wm * 4 + 2 * p + (lane >> 4)) * 8
                                      + (2 * kk + ((lane >> 3) & 1))) * 128 + (lane & 7) * 16);

            uint32_t ah[4][4], bh[4][2];
#pragma unroll
            for (int f = 0; f < 4; f++)
                ldsm4(ah[f][0], ah[f][1], ah[f][2], ah[f][3], aH + aoff[f]);
#pragma unroll
            for (int p = 0; p < 2; p++)
                ldsm4(bh[2 * p][0], bh[2 * p][1], bh[2 * p + 1][0], bh[2 * p + 1][1],
                      bH + boff[p]);
#pragma unroll
            for (int f = 0; f < 4; f++)
#pragma unroll
                for (int mf = 0; mf < 4; mf++)
                    mma16816(acc[f][mf], ah[f], bh[mf]);
            {
                uint32_t bl[4][2];
#pragma unroll
                for (int p = 0; p < 2; p++)
                    ldsm4(bl[2 * p][0], bl[2 * p][1], bl[2 * p + 1][0], bl[2 * p + 1][1],
                          bL + boff[p]);
#pragma unroll
                for (int f = 0; f < 4; f++)
#pragma unroll
                    for (int mf = 0; mf < 4; mf++)
                        mma16816(acc[f][mf], ah[f], bl[mf]);
            }
            {
#pragma unroll
                for (int f = 0; f < 4; f++) {
                    uint32_t av[4];
                    ldsm4(av[0], av[1], av[2], av[3], aL + aoff[f]);
#pragma unroll
                    for (int mf = 0; mf < 4; mf++)
                        mma16816(acc[f][mf], av, bh[mf]);
                }
            }
        }
    }
    int g = lane >> 2, t2 = (lane & 3) * 2;
#pragma unroll
    for (int f = 0; f < 4; f++) {
        int r = r0 + wr * 64 + f * 16 + g;
        float b0 = __ldg(&g_bias[r]);
        float b1 = __ldg(&g_bias[r + 8]);
#pragma unroll
        for (int mf = 0; mf < 4; mf++) {
            int m = m0 + wm * 32 + mf * 8 + t2;
            float2 v0 = make_float2(acc[f][mf][0] + b0, acc[f][mf][1] + b0);
            float2 v1 = make_float2(acc[f][mf][2] + b1, acc[f][mf][3] + b1);
            *(float2*)&g_xproj[(size_t)r * MTOT + m] = v0;
            *(float2*)&g_xproj[(size_t)(r + 8) * MTOT + m] = v1;
        }
    }
}

// ---------------- persistent tensor-core LSTM recurrence (flat critical path) ----------------
__device__ __forceinline__ float sigf(float x) { return 1.f / (1.f + expf(-x)); }

// smem byte offsets (dynamic). Per CTA: 64 rows (16 units x 4 gates) x 32 batches.
#define SW_HI   0          // W hi: 64r x 512k tiled                               (64KB)
#define SW_LO   65536      // W lo                                                 (64KB)
#define SB      131072     // h tile: hi 32KB @ +0, lo 32KB @ +32768               (64KB)
#define SP_OFF  196608     // float[64][36] preacts                                 (9216B)
#define SH_HI   205824     // bf16[32][16] h-out staging hi                          (1KB)
#define SH_LO   206848     // bf16[32][16] lo                                        (1KB)
#define SOUT    207872     // float[32][16] out staging                              (2KB)
#define SM_TOT  209920

// grid 128 CTAs (32 row-groups x 4 batch-groups) x 256 threads.
__global__ void __launch_bounds__(256, 1) lstm_tc(float* __restrict__ out) {
    extern __shared__ char sm[];
    uint32_t ub = smem_u32(sm);
    float* sP = (float*)(sm + SP_OFF);
    __nv_bfloat16* sHhi = (__nv_bfloat16*)(sm + SH_HI);
    __nv_bfloat16* sHlo = (__nv_bfloat16*)(sm + SH_LO);
    float* sOut = (float*)(sm + SOUT);
    int tid = threadIdx.x, wid = tid >> 5, lane = tid & 31;
    int wr = wid & 3;              // m-tile (gate)
    int wb = wid >> 2;             // n-half (16 batches)
    int rowg = blockIdx.x >> 2, bg = blockIdx.x & 3;
    int j0 = rowg * 16;            // units j0..j0+15
    int b0 = bg * 32;              // batches b0..b0+31

    // replay-safe monotonic generation base (only this CTA writes its word)
    unsigned gbase = *(volatile unsigned*)&g_pflag[bg][rowg];

    // tile W hi/lo into smem once: 64 rows x 512 k, 8x8-b16 tiles
    // tile (rt, kt) at (rt*64 + kt)*128 + inrow*16
#pragma unroll
    for (int q = 0; q < 32; q++) {
        int idx = q * 256 + tid;               // 0..8191
        int mat = idx >> 12;                   // 0 hi, 1 lo
        int r2 = idx & 4095;
        int lr = r2 >> 6, kseg = r2 & 63;
        int rg = (lr >> 4) * 512 + j0 + (lr & 15);   // gate*512 + unit
        uint32_t soff = (uint32_t)((((lr >> 3) * 64 + kseg) * 128 + (lr & 7) * 16)
                                   + mat * 65536);
        const __nv_bfloat16* src = mat ? g_Rlo : g_Rhi;
        *(float4*)(sm + soff) = __ldg((const float4*)(src + (size_t)rg * 512 + kseg * 8));
    }

    float c0 = 0.f, c1 = 0.f;
    int eu = tid >> 4;             // unit 0..15
    int ebb = (tid & 15) * 2;      // batch base (2 cells per thread)
    __syncthreads();

    for (int t = 0; t < TT; t++) {
        int slot = t & 3;
        const __nv_bfloat16* hbi = g_hbhi[slot];
        const __nv_bfloat16* hbl = g_hblo[slot];

        // xproj preload into registers (DRAM latency hides under flag wait + h load)
        float4 xv[2];
#pragma unroll
        for (int q = 0; q < 2; q++) {
            int idx = q * 256 + tid;           // 0..511
            int lr = idx >> 3, c4 = (idx & 7) * 4;
            int rg = (lr >> 4) * 512 + j0 + (lr & 15);
            xv[q] = __ldcg((const float4*)&g_xproj[(size_t)rg * MTOT + (size_t)t * 128
                                                   + b0 + c4]);
        }

        // wait for the 32 producers of h_state(t) in this bg-clique
        if (t > 0) {
            if (tid < 32) {
                unsigned tgt = gbase + (unsigned)t;
                while ((int)(ld_acq(&g_pflag[bg][tid]) - tgt) < 0) {}
            }
            __syncthreads();
        }

        // single-shot h load: whole 32b x 512k tile, hi+lo (64KB), 16 ops/thread
        // tile (bt, kt) at (bt*64 + kt)*128 + inrow*16
#pragma unroll
        for (int q = 0; q < 16; q++) {
            int idx = q * 256 + tid;           // 0..4095
            int mat = idx >> 11;               // 0 hi, 1 lo
            int r = idx & 2047;
            int bl = r >> 6, seg = r & 63;
            uint32_t soff = (uint32_t)(((bl >> 3) * 64 + seg) * 128 + (bl & 7) * 16
                                       + mat * 32768);
            const __nv_bfloat16* src = mat ? hbl : hbi;
            cpasync16(ub + SB + soff, src + (size_t)(b0 + bl) * 512 + seg * 8);
        }
        CP_COMMIT();

        // init sP with xproj while cp.async is in flight
#pragma unroll
        for (int q = 0; q < 2; q++) {
            int idx = q * 256 + tid;
            int lr = idx >> 3, c4 = (idx & 7) * 4;
            *(float4*)&sP[lr * 36 + c4] = xv[q];
        }

        CP_WAIT0();
        __syncthreads();

        float acc[3][2][4];                    // [hh/hl/lh][n8][4]
#pragma unroll
        for (int a = 0; a < 3; a++)
#pragma unroll
            for (int n = 0; n < 2; n++)
#pragma unroll
                for (int q = 0; q < 4; q++) acc[a][n][q] = 0.f;

#pragma unroll 8
        for (int ktl = 0; ktl < 32; ktl++) {   // k16 index over full K=512
            uint32_t aoff = (uint32_t)(((wr * 2 + ((lane >> 3) & 1)) * 64
                                        + (2 * ktl + (lane >> 4))) * 128
                                       + (lane & 7) * 16);
            uint32_t boff = (uint32_t)(((wb * 2 + (lane >> 4)) * 64
                                        + (2 * ktl + ((lane >> 3) & 1))) * 128
                                       + (lane & 7) * 16);
            uint32_t ah[4], al[4], bh[4], bl[4];
            ldsm4(ah[0], ah[1], ah[2], ah[3], ub + SW_HI + aoff);
            ldsm4(bh[0], bh[1], bh[2], bh[3], ub + SB + boff);
            ldsm4(al[0], al[1], al[2], al[3], ub + SW_LO + aoff);
            ldsm4(bl[0], bl[1], bl[2], bl[3], ub + SB + 32768 + boff);
            mma16816(acc[0][0], ah, bh + 0);
            mma16816(acc[0][1], ah, bh + 2);
            mma16816(acc[1][0], ah, bl + 0);
            mma16816(acc[1][1], ah, bl + 2);
            mma16816(acc[2][0], al, bh + 0);
            mma16816(acc[2][1], al, bh + 2);
        }

        // merge accumulators into sP right away (init visibility carried by the
        // post-WAIT0 barrier; each (row,col) has a unique owner thread)
        {
            int g = lane >> 2, t2 = (lane & 3) * 2;
            int R0 = wr * 16 + g, R1 = R0 + 8;
#pragma unroll
            for (int n = 0; n < 2; n++) {
                int C = wb * 16 + n * 8 + t2;
                sP[R0 * 36 + C]     += acc[0][n][0] + acc[1][n][0] + acc[2][n][0];
                sP[R0 * 36 + C + 1] += acc[0][n][1] + acc[1][n][1] + acc[2][n][1];
                sP[R1 * 36 + C]     += acc[0][n][2] + acc[1][n][2] + acc[2][n][2];
                sP[R1 * 36 + C + 1] += acc[0][n][3] + acc[1][n][3] + acc[2][n][3];
            }
        }
        __syncthreads();

        // cell update: thread owns unit eu, batches ebb, ebb+1
        float cc[2] = {c0, c1};
#pragma unroll
        for (int e = 0; e < 2; e++) {
            int bl = ebb + e;
            float pf = sP[(0  + eu) * 36 + bl];
            float pi = sP[(16 + eu) * 36 + bl];
            float pg = sP[(32 + eu) * 36 + bl];
            float po = sP[(48 + eu) * 36 + bl];
            float fg = sigf(pf), ig = sigf(pi), gg = tanhf(pg), og = sigf(po);
            float cn = fg * cc[e] + ig * gg;
            cc[e] = cn;
            float hv = og * tanhf(cn);
            sOut[bl * 16 + eu] = hv;
            __nv_bfloat16 hh = __float2bfloat16(hv);
            sHhi[bl * 16 + eu] = hh;
            sHlo[bl * 16 + eu] = __float2bfloat16(hv - __bfloat162float(hh));
            if (t == TT - 1) {
                out[OUTBASE + (size_t)(b0 + bl) * 512 + j0 + eu] = hv;
                out[OUTBASE + (size_t)BB * HD + (size_t)(b0 + bl) * 512 + j0 + eu] = cn;
            }
        }
        c0 = cc[0]; c1 = cc[1];
        __syncthreads();

        // h ring write (critical path) — coalesced from staging
        {
            int nslot = (t + 1) & 3;
            if (tid < 128) {
                int mat = tid >> 6;                // 0 hi, 1 lo
                int r = tid & 63;
                int b = r >> 1, half = r & 1;
                const __nv_bfloat16* s = mat ? sHlo : sHhi;
                float4 v = *(const float4*)&s[b * 16 + half * 8];
                __nv_bfloat16* dst = (mat ? g_hblo : g_hbhi)[nslot]
                                     + (size_t)(b0 + b) * 512 + j0 + half * 8;
                *(float4*)dst = v;
            }
        }
        __syncthreads();
        // release immediately: consumers can start while we do the out DRAM write
        if (tid == 0) st_rel(&g_pflag[bg][rowg], gbase + (unsigned)t + 1u);

        // out write — off the inter-CTA critical path
        {
            int b = tid >> 1, q4 = tid & 1;        // 128 batches? no: 32 b x 2 q8
            // 32 batches x 16 floats = 512 floats = 128 float4s; use tids 0..127
            if (tid < 128) {
                int bb = tid >> 2, qq = tid & 3;
                float4 v = *(const float4*)&sOut[bb * 16 + qq * 4];
                *(float4*)&out[((size_t)t * 128 + b0 + bb) * 512 + j0 + qq * 4] = v;
            }
            (void)b; (void)q4;
        }
        // NOTE: no sync needed here; next iteration's first touch of sOut/staging
        // happens after the next flag-wait __syncthreads (t+1 path) — but sP init
        // races with this tail read only through distinct buffers, and sOut is
        // re-written only after the post-merge sync of step t+1.
        __syncthreads();
    }
}

extern "C" void kernel_launch(void* const* d_in, const int* in_sizes, int n_in,
                              void* d_out, int out_size) {
    const float* X  = (const float*)d_in[0];
    const float* Wf = (const float*)d_in[1];
    const float* bf = (const float*)d_in[2];
    const float* Wi = (const float*)d_in[3];
    const float* bi = (const float*)d_in[4];
    const float* Wg = (const float*)d_in[5];
    const float* bg = (const float*)d_in[6];
    const float* Wo = (const float*)d_in[7];
    const float* bo = (const float*)d_in[8];
    float* out = (float*)d_out;

    const int mma_smem = 4 * 16384 + 128;   // ~64.1KB
    cudaFuncSetAttribute(xproj_mma, cudaFuncAttributeMaxDynamicSharedMemorySize, mma_smem);
    cudaFuncSetAttribute(lstm_tc, cudaFuncAttributeMaxDynamicSharedMemorySize, SM_TOT);

    pack_kernel<<<(NR * DIN + 255) / 256, 256>>>(Wf, Wi, Wg, Wo, bf, bi, bg, bo);
    split_x<<<(int)(((size_t)MTOT * DIN / 4 + 255) / 256), 256>>>(X);
    dim3 ggrid(MTOT / 128, NR / 128);   // (512, 16)
    xproj_mma<<<ggrid, 256, mma_smem>>>(0);
    lstm_tc<<<128, 256, SM_TOT>>>(out);
}

// round 14
// speedup vs baseline: 1.0803x; 1.0803x over previous
#include <cuda_runtime.h>
#include <cuda_bf16.h>
#include <math.h>
#include <stdint.h>

#define TT 512
#define BB 128
#define DIN 512
#define HD 512
#define NR 2048
#define MTOT (TT * BB)          // 65536
#define OUTBASE ((size_t)TT * BB * HD)

// ---------------- scratch ----------------
__device__ __nv_bfloat16 g_Xhi[(size_t)MTOT * DIN];
__device__ __nv_bfloat16 g_Xlo[(size_t)MTOT * DIN];
__device__ __nv_bfloat16 g_Whi[NR * DIN];        // x-part weights hi
__device__ __nv_bfloat16 g_Wlo[NR * DIN];        // x-part weights lo
__device__ __nv_bfloat16 g_Rhi[NR * HD];         // h-part weights hi
__device__ __nv_bfloat16 g_Rlo[NR * HD];         // h-part weights lo
__device__ float g_bias[NR];
__device__ float g_xproj[(size_t)NR * MTOT];     // [r][m]
__device__ __nv_bfloat16 g_hbhi[4][BB * HD];     // h hi, [b][k], 4-slot ring
__device__ __nv_bfloat16 g_hblo[4][BB * HD];     // h lo
__device__ unsigned g_pflag[4][32];              // [bg][rowg] monotonic step flags

// ---------------- PTX helpers (sm_80-compatible ISA only) ----------------
__device__ __forceinline__ uint32_t smem_u32(const void* p) {
    uint32_t a;
    asm("{ .reg .u64 t; cvta.to.shared.u64 t, %1; cvt.u32.u64 %0, t; }" : "=r"(a) : "l"(p));
    return a;
}

__device__ __forceinline__ void ldsm4(uint32_t& r0, uint32_t& r1, uint32_t& r2, uint32_t& r3,
                                      uint32_t addr) {
    asm volatile("ldmatrix.sync.aligned.m8n8.x4.shared.b16 {%0,%1,%2,%3}, [%4];"
                 : "=r"(r0), "=r"(r1), "=r"(r2), "=r"(r3) : "r"(addr));
}

__device__ __forceinline__ void mma16816(float* c, const uint32_t* a, const uint32_t* b) {
    asm volatile("mma.sync.aligned.m16n8k16.row.col.f32.bf16.bf16.f32 "
                 "{%0,%1,%2,%3}, {%4,%5,%6,%7}, {%8,%9}, {%0,%1,%2,%3};"
                 : "+f"(c[0]), "+f"(c[1]), "+f"(c[2]), "+f"(c[3])
                 : "r"(a[0]), "r"(a[1]), "r"(a[2]), "r"(a[3]), "r"(b[0]), "r"(b[1]));
}

__device__ __forceinline__ void cpasync16(uint32_t saddr, const void* g) {
    asm volatile("cp.async.cg.shared.global [%0], [%1], 16;" :: "r"(saddr), "l"(g));
}
#define CP_COMMIT() asm volatile("cp.async.commit_group;" ::: "memory")
#define CP_WAIT1()  asm volatile("cp.async.wait_group 1;" ::: "memory")
#define CP_WAIT0()  asm volatile("cp.async.wait_group 0;" ::: "memory")

__device__ __forceinline__ unsigned ld_acq(const unsigned* p) {
    unsigned v;
    asm volatile("ld.acquire.gpu.global.u32 %0, [%1];" : "=r"(v) : "l"(p) : "memory");
    return v;
}
__device__ __forceinline__ void st_rel(unsigned* p, unsigned v) {
    asm volatile("st.release.gpu.global.u32 [%0], %1;" :: "l"(p), "r"(v) : "memory");
}

// ---------------- pack weights (bf16 hi/lo both halves), zero h0 ----------------
__global__ void pack_kernel(const float* __restrict__ Wf, const float* __restrict__ Wi,
                            const float* __restrict__ Wg_, const float* __restrict__ Wo,
                            const float* __restrict__ bf, const float* __restrict__ bi,
                            const float* __restrict__ bg, const float* __restrict__ bo) {
    int idx = blockIdx.x * blockDim.x + threadIdx.x;
    if (idx < NR * DIN) {
        int r = idx >> 9;
        int k = idx & 511;
        int gate = r >> 9;
        int j = r & 511;
        const float* W = (gate == 0) ? Wf : (gate == 1) ? Wi : (gate == 2) ? Wg_ : Wo;
        float wx = W[j * 1024 + k];
        __nv_bfloat16 hi = __float2bfloat16(wx);
        g_Whi[idx] = hi;
        g_Wlo[idx] = __float2bfloat16(wx - __bfloat162float(hi));
        float wh = W[j * 1024 + 512 + k];
        __nv_bfloat16 rh = __float2bfloat16(wh);
        g_Rhi[idx] = rh;
        g_Rlo[idx] = __float2bfloat16(wh - __bfloat162float(rh));
        if (k == 0) {
            const float* bb = (gate == 0) ? bf : (gate == 1) ? bi : (gate == 2) ? bg : bo;
            g_bias[r] = bb[j];
        }
    }
    if (idx < BB * HD) {
        g_hbhi[0][idx] = __float2bfloat16(0.f);
        g_hblo[0][idx] = __float2bfloat16(0.f);
    }
}

// ---------------- split X into bf16 hi/lo ----------------
__global__ void split_x(const float* __restrict__ X) {
    size_t i = (size_t)blockIdx.x * blockDim.x + threadIdx.x;  // float4 index
    if (i < (size_t)MTOT * DIN / 4) {
        float4 v = __ldg((const float4*)X + i);
        __nv_bfloat16 h0 = __float2bfloat16(v.x), h1 = __float2bfloat16(v.y);
        __nv_bfloat16 h2 = __float2bfloat16(v.z), h3 = __float2bfloat16(v.w);
        __nv_bfloat162* ph = (__nv_bfloat162*)g_Xhi;
        __nv_bfloat162* pl = (__nv_bfloat162*)g_Xlo;
        ph[i * 2] = __nv_bfloat162(h0, h1);
        ph[i * 2 + 1] = __nv_bfloat162(h2, h3);
        pl[i * 2] = __nv_bfloat162(__float2bfloat16(v.x - __bfloat162float(h0)),
                                   __float2bfloat16(v.y - __bfloat162float(h1)));
        pl[i * 2 + 1] = __nv_bfloat162(__float2bfloat16(v.z - __bfloat162float(h2)),
                                       __float2bfloat16(v.w - __bfloat162float(h3)));
    }
}

// ---------------- xproj via mma.sync (proven in R8) ----------------
__global__ void __launch_bounds__(256) xproj_mma(int dummy) {
    extern __shared__ char smraw[];
    char* smp = (char*)(((uintptr_t)smraw + 127) & ~(uintptr_t)127);
    uint32_t ub = smem_u32(smp);
    int tid = threadIdx.x, wid = tid >> 5, lane = tid & 31;
    int wr = wid & 1, wm = wid >> 1;
    int r0 = blockIdx.y * 128, m0 = blockIdx.x * 128;

    float acc[4][4][4];
#pragma unroll
    for (int f = 0; f < 4; f++)
#pragma unroll
        for (int mf = 0; mf < 4; mf++)
#pragma unroll
            for (int q = 0; q < 4; q++) acc[f][mf][q] = 0.f;

    const __nv_bfloat16* srcs[4] = {
        g_Whi + (size_t)r0 * DIN, g_Wlo + (size_t)r0 * DIN,
        g_Xhi + (size_t)m0 * DIN, g_Xlo + (size_t)m0 * DIN };

    for (int kc = 0; kc < 8; kc++) {
        __syncthreads();
#pragma unroll
        for (int mat = 0; mat < 4; mat++) {
            const float4* src = (const float4*)srcs[mat];
            char* dst = smp + mat * 16384;
#pragma unroll
            for (int it = 0; it < 4; it++) {
                int idx = tid + it * 256;
                int row = idx & 127;
                int kt8 = idx >> 7;
                uint32_t off = (uint32_t)(((row >> 3) * 8 + kt8) * 128 + (row & 7) * 16);
                *(float4*)(dst + off) = __ldg(src + (size_t)row * 64 + kc * 8 + kt8);
            }
        }
        __syncthreads();
        uint32_t aH = ub, aL = ub + 16384, bH = ub + 32768, bL = ub + 49152;
#pragma unroll
        for (int kk = 0; kk < 4; kk++) {
            uint32_t aoff[4], boff[2];
#pragma unroll
            for (int f = 0; f < 4; f++)
                aoff[f] = (uint32_t)(((wr * 8 + f * 2 + ((lane >> 3) & 1)) * 8
                                      + (2 * kk + (lane >> 4))) * 128 + (lane & 7) * 16);
#pragma unroll
            for (int p = 0; p < 2; p++)
                boff[p] = (uint32_t)(((wm * 4 + 2 * p + (lane >> 4)) * 8
                                      + (2 * kk + ((lane >> 3) & 1))) * 128 + (lane & 7) * 16);

            uint32_t ah[4][4], bh[4][2];
#pragma unroll
            for (int f = 0; f < 4; f++)
                ldsm4(ah[f][0], ah[f][1], ah[f][2], ah[f][3], aH + aoff[f]);
#pragma unroll
            for (int p = 0; p < 2; p++)
                ldsm4(bh[2 * p][0], bh[2 * p][1], bh[2 * p + 1][0], bh[2 * p + 1][1],
                      bH + boff[p]);
#pragma unroll
            for (int f = 0; f < 4; f++)
#pragma unroll
                for (int mf = 0; mf < 4; mf++)
                    mma16816(acc[f][mf], ah[f], bh[mf]);
            {
                uint32_t bl[4][2];
#pragma unroll
                for (int p = 0; p < 2; p++)
                    ldsm4(bl[2 * p][0], bl[2 * p][1], bl[2 * p + 1][0], bl[2 * p + 1][1],
                          bL + boff[p]);
#pragma unroll
                for (int f = 0; f < 4; f++)
#pragma unroll
                    for (int mf = 0; mf < 4; mf++)
                        mma16816(acc[f][mf], ah[f], bl[mf]);
            }
            {
#pragma unroll
                for (int f = 0; f < 4; f++) {
                    uint32_t av[4];
                    ldsm4(av[0], av[1], av[2], av[3], aL + aoff[f]);
#pragma unroll
                    for (int mf = 0; mf < 4; mf++)
                        mma16816(acc[f][mf], av, bh[mf]);
                }
            }
        }
    }
    int g = lane >> 2, t2 = (lane & 3) * 2;
#pragma unroll
    for (int f = 0; f < 4; f++) {
        int r = r0 + wr * 64 + f * 16 + g;
        float b0 = __ldg(&g_bias[r]);
        float b1 = __ldg(&g_bias[r + 8]);
#pragma unroll
        for (int mf = 0; mf < 4; mf++) {
            int m = m0 + wm * 32 + mf * 8 + t2;
            float2 v0 = make_float2(acc[f][mf][0] + b0, acc[f][mf][1] + b0);
            float2 v1 = make_float2(acc[f][mf][2] + b1, acc[f][mf][3] + b1);
            *(float2*)&g_xproj[(size_t)r * MTOT + m] = v0;
            *(float2*)&g_xproj[(size_t)(r + 8) * MTOT + m] = v1;
        }
    }
}

// ---------------- persistent tensor-core LSTM recurrence (wavefront flags) ----------------
__device__ __forceinline__ float sigf(float x) { return 1.f / (1.f + expf(-x)); }

// smem byte offsets (dynamic). Per CTA: 64 rows (16 units x 4 gates) x 32 batches.
#define SW_HI   0          // W hi: 64r x 512k tiled                               (64KB)
#define SW_LO   65536      // W lo                                                 (64KB)
#define SB_BASE 131072     // h chunks: 3 bufs x 16KB (hi 8KB + lo 8KB)            (48KB)
#define SP_OFF  180224     // float[64][36] preacts                                 (9216B)
#define SH_HI   189440     // bf16[32][16] h-out staging hi                          (1KB)
#define SH_LO   190464     // bf16[32][16] lo                                        (1KB)
#define SOUT    191488     // float[32][16] out staging                              (2KB)
#define SM_TOT  193536

// chunk kc: k in [kc*128, kc*128+128), batches b0..b0+31, hi+lo (16KB)
__device__ __forceinline__ void issue_chunk(uint32_t sbuf, const __nv_bfloat16* hbi,
                                            const __nv_bfloat16* hbl, int b0, int kc, int tid) {
#pragma unroll
    for (int q = 0; q < 4; q++) {
        int idx = q * 256 + tid;               // 0..1023
        int mat = idx >> 9;                    // 0 hi, 1 lo
        int r = idx & 511;
        int bl = r >> 4, seg = r & 15;         // 16B op covers 8 k = one tile row
        uint32_t soff = (uint32_t)((((bl >> 3) * 16 + seg) * 128 + (bl & 7) * 16)
                                   + mat * 8192);
        const __nv_bfloat16* src = mat ? hbl : hbi;
        cpasync16(sbuf + soff, src + (size_t)(b0 + bl) * 512 + kc * 128 + seg * 8);
    }
}

// grid 128 CTAs (32 row-groups x 4 batch-groups) x 256 threads.
__global__ void __launch_bounds__(256, 1) lstm_tc(float* __restrict__ out) {
    extern __shared__ char sm[];
    uint32_t ub = smem_u32(sm);
    float* sP = (float*)(sm + SP_OFF);
    __nv_bfloat16* sHhi = (__nv_bfloat16*)(sm + SH_HI);
    __nv_bfloat16* sHlo = (__nv_bfloat16*)(sm + SH_LO);
    float* sOut = (float*)(sm + SOUT);
    int tid = threadIdx.x, wid = tid >> 5, lane = tid & 31;
    int wr = wid & 3;              // m-tile (gate)
    int wb = wid >> 2;             // n-half (16 batches)
    int rowg = blockIdx.x >> 2, bg = blockIdx.x & 3;
    int j0 = rowg * 16;            // units j0..j0+15
    int b0 = bg * 32;              // batches b0..b0+31

    // replay-safe monotonic generation base (only this CTA writes its word)
    unsigned gbase = *(volatile unsigned*)&g_pflag[bg][rowg];

    // tile W hi/lo into smem once: 64 rows x 512 k, 8x8-b16 tiles
#pragma unroll
    for (int q = 0; q < 32; q++) {
        int idx = q * 256 + tid;               // 0..8191
        int mat = idx >> 12;                   // 0 hi, 1 lo
        int r2 = idx & 4095;
        int lr = r2 >> 6, kseg = r2 & 63;
        int rg = (lr >> 4) * 512 + j0 + (lr & 15);   // gate*512 + unit
        uint32_t soff = (uint32_t)((((lr >> 3) * 64 + kseg) * 128 + (lr & 7) * 16)
                                   + mat * 65536);
        const __nv_bfloat16* src = mat ? g_Rlo : g_Rhi;
        *(float4*)(sm + soff) = __ldg((const float4*)(src + (size_t)rg * 512 + kseg * 8));
    }

    float c0 = 0.f, c1 = 0.f;
    int eu = tid >> 4;             // unit 0..15
    int ebb = (tid & 15) * 2;      // batch base (2 cells per thread)
    __syncthreads();

    for (int t = 0; t < TT; t++) {
        int slot = t & 3;
        const __nv_bfloat16* hbi = g_hbhi[slot];
        const __nv_bfloat16* hbl = g_hblo[slot];

        // xproj preload into registers (DRAM latency hides under flag wait + pipeline)
        float4 xv[2];
#pragma unroll
        for (int q = 0; q < 2; q++) {
            int idx = q * 256 + tid;           // 0..511
            int lr = idx >> 3, c4 = (idx & 7) * 4;
            int rg = (lr >> 4) * 512 + j0 + (lr & 15);
            xv[q] = __ldcg((const float4*)&g_xproj[(size_t)rg * MTOT + (size_t)t * 128
                                                   + b0 + c4]);
        }

        // wavefront prologue: wait only producers of chunks 0,1 (rowg 0..15)
        if (t > 0) {
            if (tid < 16) {
                unsigned tgt = gbase + (unsigned)t;
                while ((int)(ld_acq(&g_pflag[bg][tid]) - tgt) < 0) {}
            }
            __syncthreads();
        }

        // prologue: chunks 0,1
        issue_chunk(ub + SB_BASE, hbi, hbl, b0, 0, tid);
        CP_COMMIT();
        issue_chunk(ub + SB_BASE + 16384, hbi, hbl, b0, 1, tid);
        CP_COMMIT();

        // init sP with xproj while cp.async is in flight (ordered by loop's syncs)
#pragma unroll
        for (int q = 0; q < 2; q++) {
            int idx = q * 256 + tid;
            int lr = idx >> 3, c4 = (idx & 7) * 4;
            *(float4*)&sP[lr * 36 + c4] = xv[q];
        }

        float acc[3][2][4];                    // [hh/hl/lh][n8][4]
#pragma unroll
        for (int a = 0; a < 3; a++)
#pragma unroll
            for (int n = 0; n < 2; n++)
#pragma unroll
                for (int q = 0; q < 4; q++) acc[a][n][q] = 0.f;

        for (int kc = 0; kc < 4; kc++) {
            if (kc < 3) { CP_WAIT1(); } else { CP_WAIT0(); }
            __syncthreads();
            // poll next group's producers (warp0 lanes) while MMA runs below
            if (t > 0 && kc + 2 < 4 && tid < 8) {
                unsigned tgt = gbase + (unsigned)t;
                while ((int)(ld_acq(&g_pflag[bg][8 * (kc + 2) + tid]) - tgt) < 0) {}
            }
            uint32_t bb = ub + SB_BASE + (kc % 3) * 16384;
#pragma unroll
            for (int ktl = 0; ktl < 8; ktl++) {
                int ktg = kc * 8 + ktl;        // global k16 index 0..31
                uint32_t aoff = (uint32_t)(((wr * 2 + ((lane >> 3) & 1)) * 64
                                            + (2 * ktg + (lane >> 4))) * 128
                                           + (lane & 7) * 16);
                uint32_t boff = (uint32_t)(((wb * 2 + (lane >> 4)) * 16
                                            + (2 * ktl + ((lane >> 3) & 1))) * 128
                                           + (lane & 7) * 16);
                uint32_t ah[4], al[4], bh[4], bl[4];
                ldsm4(ah[0], ah[1], ah[2], ah[3], ub + SW_HI + aoff);
                ldsm4(bh[0], bh[1], bh[2], bh[3], bb + boff);
                ldsm4(al[0], al[1], al[2], al[3], ub + SW_LO + aoff);
                ldsm4(bl[0], bl[1], bl[2], bl[3], bb + 8192 + boff);
                mma16816(acc[0][0], ah, bh + 0);
                mma16816(acc[0][1], ah, bh + 2);
                mma16816(acc[1][0], ah, bl + 0);
                mma16816(acc[1][1], ah, bl + 2);
                mma16816(acc[2][0], al, bh + 0);
                mma16816(acc[2][1], al, bh + 2);
            }
            if (kc + 2 < 4) {
                __syncthreads();               // MMA on reused buffer done; flags passed
                issue_chunk(ub + SB_BASE + ((kc + 2) % 3) * 16384, hbi, hbl, b0, kc + 2, tid);
                CP_COMMIT();
            }
        }

        // merge accumulators into sP (unique (row,col) owner; init ordered by loop syncs)
        {
            int g = lane >> 2, t2 = (lane & 3) * 2;
            int R0 = wr * 16 + g, R1 = R0 + 8;
#pragma unroll
            for (int n = 0; n < 2; n++) {
                int C = wb * 16 + n * 8 + t2;
                sP[R0 * 36 + C]     += acc[0][n][0] + acc[1][n][0] + acc[2][n][0];
                sP[R0 * 36 + C + 1] += acc[0][n][1] + acc[1][n][1] + acc[2][n][1];
                sP[R1 * 36 + C]     += acc[0][n][2] + acc[1][n][2] + acc[2][n][2];
                sP[R1 * 36 + C + 1] += acc[0][n][3] + acc[1][n][3] + acc[2][n][3];
            }
        }
        __syncthreads();

        // cell update: thread owns unit eu, batches ebb, ebb+1
        float cc[2] = {c0, c1};
#pragma unroll
        for (int e = 0; e < 2; e++) {
            int bl = ebb + e;
            float pf = sP[(0  + eu) * 36 + bl];
            float pi = sP[(16 + eu) * 36 + bl];
            float pg = sP[(32 + eu) * 36 + bl];
            float po = sP[(48 + eu) * 36 + bl];
            float fg = sigf(pf), ig = sigf(pi), gg = tanhf(pg), og = sigf(po);
            float cn = fg * cc[e] + ig * gg;
            cc[e] = cn;
            float hv = og * tanhf(cn);
            sOut[bl * 16 + eu] = hv;
            __nv_bfloat16 hh = __float2bfloat16(hv);
            sHhi[bl * 16 + eu] = hh;
            sHlo[bl * 16 + eu] = __float2bfloat16(hv - __bfloat162float(hh));
            if (t == TT - 1) {
                out[OUTBASE + (size_t)(b0 + bl) * 512 + j0 + eu] = hv;
                out[OUTBASE + (size_t)BB * HD + (size_t)(b0 + bl) * 512 + j0 + eu] = cn;
            }
        }
        c0 = cc[0]; c1 = cc[1];
        __syncthreads();

        // h ring write (critical path) — coalesced from staging
        {
            int nslot = (t + 1) & 3;
            if (tid < 128) {
                int mat = tid >> 6;                // 0 hi, 1 lo
                int r = tid & 63;
                int b = r >> 1, half = r & 1;
                const __nv_bfloat16* s = mat ? sHlo : sHhi;
                float4 v = *(const float4*)&s[b * 16 + half * 8];
                __nv_bfloat16* dst = (mat ? g_hblo : g_hbhi)[nslot]
                                     + (size_t)(b0 + b) * 512 + j0 + half * 8;
                *(float4*)dst = v;
            }
        }
        __syncthreads();
        // release first — consumers proceed while we do the out DRAM write
        if (tid == 0) st_rel(&g_pflag[bg][rowg], gbase + (unsigned)t + 1u);

        // out write — off the inter-CTA critical path
        if (tid < 128) {
            int bb2 = tid >> 2, qq = tid & 3;
            float4 v = *(const float4*)&sOut[bb2 * 16 + qq * 4];
            *(float4*)&out[((size_t)t * 128 + b0 + bb2) * 512 + j0 + qq * 4] = v;
        }
        __syncthreads();
    }
}

extern "C" void kernel_launch(void* const* d_in, const int* in_sizes, int n_in,
                              void* d_out, int out_size) {
    const float* X  = (const float*)d_in[0];
    const float* Wf = (const float*)d_in[1];
    const float* bf = (const float*)d_in[2];
    const float* Wi = (const float*)d_in[3];
    const float* bi = (const float*)d_in[4];
    const float* Wg = (const float*)d_in[5];
    const float* bg = (const float*)d_in[6];
    const float* Wo = (const float*)d_in[7];
    const float* bo = (const float*)d_in[8];
    float* out = (float*)d_out;

    const int mma_smem = 4 * 16384 + 128;   // ~64.1KB
    cudaFuncSetAttribute(xproj_mma, cudaFuncAttributeMaxDynamicSharedMemorySize, mma_smem);
    cudaFuncSetAttribute(lstm_tc, cudaFuncAttributeMaxDynamicSharedMemorySize, SM_TOT);

    pack_kernel<<<(NR * DIN + 255) / 256, 256>>>(Wf, Wi, Wg, Wo, bf, bi, bg, bo);
    split_x<<<(int)(((size_t)MTOT * DIN / 4 + 255) / 256), 256>>>(X);
    dim3 ggrid(MTOT / 128, NR / 128);   // (512, 16)
    xproj_mma<<<ggrid, 256, mma_smem>>>(0);
    lstm_tc<<<128, 256, SM_TOT>>>(out);
}

// round 15
// speedup vs baseline: 1.1579x; 1.0719x over previous
#include <cuda_runtime.h>
#include <cuda_bf16.h>
#include <math.h>
#include <stdint.h>

#define TT 512
#define BB 128
#define DIN 512
#define HD 512
#define NR 2048
#define MTOT (TT * BB)          // 65536
#define OUTBASE ((size_t)TT * BB * HD)

// ---------------- scratch ----------------
__device__ __nv_bfloat16 g_Xhi[(size_t)MTOT * DIN];
__device__ __nv_bfloat16 g_Xlo[(size_t)MTOT * DIN];
__device__ __nv_bfloat16 g_Whi[NR * DIN];        // x-part weights hi
__device__ __nv_bfloat16 g_Wlo[NR * DIN];        // x-part weights lo
__device__ __nv_bfloat16 g_Rhi[NR * HD];         // h-part weights hi
__device__ __nv_bfloat16 g_Rlo[NR * HD];         // h-part weights lo
__device__ float g_bias[NR];
__device__ float g_xproj[(size_t)NR * MTOT];     // [r][m]
__device__ __nv_bfloat16 g_hbhi[4][BB * HD];     // h hi, [b][k], 4-slot ring
__device__ __nv_bfloat16 g_hblo[4][BB * HD];     // h lo
__device__ unsigned g_pflag[4][32];              // [bg][rowg] monotonic step flags

// ---------------- PTX helpers (sm_80-compatible ISA only) ----------------
__device__ __forceinline__ uint32_t smem_u32(const void* p) {
    uint32_t a;
    asm("{ .reg .u64 t; cvta.to.shared.u64 t, %1; cvt.u32.u64 %0, t; }" : "=r"(a) : "l"(p));
    return a;
}

__device__ __forceinline__ void ldsm4(uint32_t& r0, uint32_t& r1, uint32_t& r2, uint32_t& r3,
                                      uint32_t addr) {
    asm volatile("ldmatrix.sync.aligned.m8n8.x4.shared.b16 {%0,%1,%2,%3}, [%4];"
                 : "=r"(r0), "=r"(r1), "=r"(r2), "=r"(r3) : "r"(addr));
}

__device__ __forceinline__ void mma16816(float* c, const uint32_t* a, const uint32_t* b) {
    asm volatile("mma.sync.aligned.m16n8k16.row.col.f32.bf16.bf16.f32 "
                 "{%0,%1,%2,%3}, {%4,%5,%6,%7}, {%8,%9}, {%0,%1,%2,%3};"
                 : "+f"(c[0]), "+f"(c[1]), "+f"(c[2]), "+f"(c[3])
                 : "r"(a[0]), "r"(a[1]), "r"(a[2]), "r"(a[3]), "r"(b[0]), "r"(b[1]));
}

__device__ __forceinline__ void cpasync16(uint32_t saddr, const void* g) {
    asm volatile("cp.async.cg.shared.global [%0], [%1], 16;" :: "r"(saddr), "l"(g));
}
#define CP_COMMIT() asm volatile("cp.async.commit_group;" ::: "memory")
#define CP_WAIT1()  asm volatile("cp.async.wait_group 1;" ::: "memory")
#define CP_WAIT0()  asm volatile("cp.async.wait_group 0;" ::: "memory")

__device__ __forceinline__ unsigned ld_acq(const unsigned* p) {
    unsigned v;
    asm volatile("ld.acquire.gpu.global.u32 %0, [%1];" : "=r"(v) : "l"(p) : "memory");
    return v;
}
__device__ __forceinline__ void st_rel(unsigned* p, unsigned v) {
    asm volatile("st.release.gpu.global.u32 [%0], %1;" :: "l"(p), "r"(v) : "memory");
}

// ---------------- pack weights (bf16 hi/lo both halves), zero h0 ----------------
__global__ void pack_kernel(const float* __restrict__ Wf, const float* __restrict__ Wi,
                            const float* __restrict__ Wg_, const float* __restrict__ Wo,
                            const float* __restrict__ bf, const float* __restrict__ bi,
                            const float* __restrict__ bg, const float* __restrict__ bo) {
    int idx = blockIdx.x * blockDim.x + threadIdx.x;
    if (idx < NR * DIN) {
        int r = idx >> 9;
        int k = idx & 511;
        int gate = r >> 9;
        int j = r & 511;
        const float* W = (gate == 0) ? Wf : (gate == 1) ? Wi : (gate == 2) ? Wg_ : Wo;
        float wx = W[j * 1024 + k];
        __nv_bfloat16 hi = __float2bfloat16(wx);
        g_Whi[idx] = hi;
        g_Wlo[idx] = __float2bfloat16(wx - __bfloat162float(hi));
        float wh = W[j * 1024 + 512 + k];
        __nv_bfloat16 rh = __float2bfloat16(wh);
        g_Rhi[idx] = rh;
        g_Rlo[idx] = __float2bfloat16(wh - __bfloat162float(rh));
        if (k == 0) {
            const float* bb = (gate == 0) ? bf : (gate == 1) ? bi : (gate == 2) ? bg : bo;
            g_bias[r] = bb[j];
        }
    }
    if (idx < BB * HD) {
        g_hbhi[0][idx] = __float2bfloat16(0.f);
        g_hblo[0][idx] = __float2bfloat16(0.f);
    }
}

// ---------------- split X into bf16 hi/lo ----------------
__global__ void split_x(const float* __restrict__ X) {
    size_t i = (size_t)blockIdx.x * blockDim.x + threadIdx.x;  // float4 index
    if (i < (size_t)MTOT * DIN / 4) {
        float4 v = __ldg((const float4*)X + i);
        __nv_bfloat16 h0 = __float2bfloat16(v.x), h1 = __float2bfloat16(v.y);
        __nv_bfloat16 h2 = __float2bfloat16(v.z), h3 = __float2bfloat16(v.w);
        __nv_bfloat162* ph = (__nv_bfloat162*)g_Xhi;
        __nv_bfloat162* pl = (__nv_bfloat162*)g_Xlo;
        ph[i * 2] = __nv_bfloat162(h0, h1);
        ph[i * 2 + 1] = __nv_bfloat162(h2, h3);
        pl[i * 2] = __nv_bfloat162(__float2bfloat16(v.x - __bfloat162float(h0)),
                                   __float2bfloat16(v.y - __bfloat162float(h1)));
        pl[i * 2 + 1] = __nv_bfloat162(__float2bfloat16(v.z - __bfloat162float(h2)),
                                       __float2bfloat16(v.w - __bfloat162float(h3)));
    }
}

// ---------------- xproj via mma.sync (proven in R8) ----------------
__global__ void __launch_bounds__(256) xproj_mma(int dummy) {
    extern __shared__ char smraw[];
    char* smp = (char*)(((uintptr_t)smraw + 127) & ~(uintptr_t)127);
    uint32_t ub = smem_u32(smp);
    int tid = threadIdx.x, wid = tid >> 5, lane = tid & 31;
    int wr = wid & 1, wm = wid >> 1;
    int r0 = blockIdx.y * 128, m0 = blockIdx.x * 128;

    float acc[4][4][4];
#pragma unroll
    for (int f = 0; f < 4; f++)
#pragma unroll
        for (int mf = 0; mf < 4; mf++)
#pragma unroll
            for (int q = 0; q < 4; q++) acc[f][mf][q] = 0.f;

    const __nv_bfloat16* srcs[4] = {
        g_Whi + (size_t)r0 * DIN, g_Wlo + (size_t)r0 * DIN,
        g_Xhi + (size_t)m0 * DIN, g_Xlo + (size_t)m0 * DIN };

    for (int kc = 0; kc < 8; kc++) {
        __syncthreads();
#pragma unroll
        for (int mat = 0; mat < 4; mat++) {
            const float4* src = (const float4*)srcs[mat];
            char* dst = smp + mat * 16384;
#pragma unroll
            for (int it = 0; it < 4; it++) {
                int idx = tid + it * 256;
                int row = idx & 127;
                int kt8 = idx >> 7;
                uint32_t off = (uint32_t)(((row >> 3) * 8 + kt8) * 128 + (row & 7) * 16);
                *(float4*)(dst + off) = __ldg(src + (size_t)row * 64 + kc * 8 + kt8);
            }
        }
        __syncthreads();
        uint32_t aH = ub, aL = ub + 16384, bH = ub + 32768, bL = ub + 49152;
#pragma unroll
        for (int kk = 0; kk < 4; kk++) {
            uint32_t aoff[4], boff[2];
#pragma unroll
            for (int f = 0; f < 4; f++)
                aoff[f] = (uint32_t)(((wr * 8 + f * 2 + ((lane >> 3) & 1)) * 8
                                      + (2 * kk + (lane >> 4))) * 128 + (lane & 7) * 16);
#pragma unroll
            for (int p = 0; p < 2; p++)
                boff[p] = (uint32_t)(((wm * 4 + 2 * p + (lane >> 4)) * 8
                                      + (2 * kk + ((lane >> 3) & 1))) * 128 + (lane & 7) * 16);

            uint32_t ah[4][4], bh[4][2];
#pragma unroll
            for (int f = 0; f < 4; f++)
                ldsm4(ah[f][0], ah[f][1], ah[f][2], ah[f][3], aH + aoff[f]);
#pragma unroll
            for (int p = 0; p < 2; p++)
                ldsm4(bh[2 * p][0], bh[2 * p][1], bh[2 * p + 1][0], bh[2 * p + 1][1],
                      bH + boff[p]);
#pragma unroll
            for (int f = 0; f < 4; f++)
#pragma unroll
                for (int mf = 0; mf < 4; mf++)
                    mma16816(acc[f][mf], ah[f], bh[mf]);
            {
                uint32_t bl[4][2];
#pragma unroll
                for (int p = 0; p < 2; p++)
                    ldsm4(bl[2 * p][0], bl[2 * p][1], bl[2 * p + 1][0], bl[2 * p + 1][1],
                          bL + boff[p]);
#pragma unroll
                for (int f = 0; f < 4; f++)
#pragma unroll
                    for (int mf = 0; mf < 4; mf++)
                        mma16816(acc[f][mf], ah[f], bl[mf]);
            }
            {
#pragma unroll
                for (int f = 0; f < 4; f++) {
                    uint32_t av[4];
                    ldsm4(av[0], av[1], av[2], av[3], aL + aoff[f]);
#pragma unroll
                    for (int mf = 0; mf < 4; mf++)
                        mma16816(acc[f][mf], av, bh[mf]);
                }
            }
        }
    }
    int g = lane >> 2, t2 = (lane & 3) * 2;
#pragma unroll
    for (int f = 0; f < 4; f++) {
        int r = r0 + wr * 64 + f * 16 + g;
        float b0 = __ldg(&g_bias[r]);
        float b1 = __ldg(&g_bias[r + 8]);
#pragma unroll
        for (int mf = 0; mf < 4; mf++) {
            int m = m0 + wm * 32 + mf * 8 + t2;
            float2 v0 = make_float2(acc[f][mf][0] + b0, acc[f][mf][1] + b0);
            float2 v1 = make_float2(acc[f][mf][2] + b1, acc[f][mf][3] + b1);
            *(float2*)&g_xproj[(size_t)r * MTOT + m] = v0;
            *(float2*)&g_xproj[(size_t)(r + 8) * MTOT + m] = v1;
        }
    }
}

// ---------------- persistent tensor-core LSTM recurrence (in-warp epilogue) ----------------
__device__ __forceinline__ float sigf(float x) { return 1.f / (1.f + expf(-x)); }

// smem byte offsets (dynamic). Per CTA: 64 rows (16 units x 4 gates) x 32 batches.
// Local row ordering: row' = unit*4 + gate  (gate quartet warp-local!)
#define SW_HI   0          // W hi: 64r x 512k tiled                               (64KB)
#define SW_LO   65536      // W lo                                                 (64KB)
#define SB_BASE 131072     // h chunks: 3 bufs x 16KB (hi 8KB + lo 8KB)            (48KB)
#define SXC     180224     // warp-exchange: 8 warps x 1KB                          (8KB)
#define SH_HI   189440     // bf16[32][16] h-out staging hi                          (1KB)
#define SH_LO   190464     // bf16[32][16] lo                                        (1KB)
#define SOUT    191488     // float[32][16] out staging                              (2KB)
#define SM_TOT  193536

// chunk kc: k in [kc*128, kc*128+128), batches b0..b0+31, hi+lo (16KB)
__device__ __forceinline__ void issue_chunk(uint32_t sbuf, const __nv_bfloat16* hbi,
                                            const __nv_bfloat16* hbl, int b0, int kc, int tid) {
#pragma unroll
    for (int q = 0; q < 4; q++) {
        int idx = q * 256 + tid;               // 0..1023
        int mat = idx >> 9;                    // 0 hi, 1 lo
        int r = idx & 511;
        int bl = r >> 4, seg = r & 15;         // 16B op covers 8 k = one tile row
        uint32_t soff = (uint32_t)((((bl >> 3) * 16 + seg) * 128 + (bl & 7) * 16)
                                   + mat * 8192);
        const __nv_bfloat16* src = mat ? hbl : hbi;
        cpasync16(sbuf + soff, src + (size_t)(b0 + bl) * 512 + kc * 128 + seg * 8);
    }
}

// grid 128 CTAs (32 row-groups x 4 batch-groups) x 256 threads.
__global__ void __launch_bounds__(256, 1) lstm_tc(float* __restrict__ out) {
    extern __shared__ char sm[];
    uint32_t ub = smem_u32(sm);
    __nv_bfloat16* sHhi = (__nv_bfloat16*)(sm + SH_HI);
    __nv_bfloat16* sHlo = (__nv_bfloat16*)(sm + SH_LO);
    float* sOut = (float*)(sm + SOUT);
    int tid = threadIdx.x, wid = tid >> 5, lane = tid & 31;
    int wr = wid & 3;              // m-tile: units wr*4..wr*4+3 (x4 gates = 16 rows)
    int wb = wid >> 2;             // n-half (16 batches)
    int rowg = blockIdx.x >> 2, bg = blockIdx.x & 3;
    int j0 = rowg * 16;            // units j0..j0+15
    int b0 = bg * 32;              // batches b0..b0+31
    int qq2 = lane >> 4;           // unit-quad half (0,1)
    int gt = (lane >> 2) & 3;      // gate owned by this lane's A-fragment rows
    int tg = lane & 3;

    // replay-safe monotonic generation base (only this CTA writes its word)
    unsigned gbase = *(volatile unsigned*)&g_pflag[bg][rowg];

    // tile W hi/lo into smem once: 64 rows x 512 k, 8x8-b16 tiles
    // local row lr = unit*4 + gate  ->  global gate row = gate*512 + j0 + unit
#pragma unroll
    for (int q = 0; q < 32; q++) {
        int idx = q * 256 + tid;               // 0..8191
        int mat = idx >> 12;                   // 0 hi, 1 lo
        int r2 = idx & 4095;
        int lr = r2 >> 6, kseg = r2 & 63;
        int rg = (lr & 3) * 512 + j0 + (lr >> 2);
        uint32_t soff = (uint32_t)((((lr >> 3) * 64 + kseg) * 128 + (lr & 7) * 16)
                                   + mat * 65536);
        const __nv_bfloat16* src = mat ? g_Rlo : g_Rhi;
        *(float4*)(sm + soff) = __ldg((const float4*)(src + (size_t)rg * 512 + kseg * 8));
    }

    float cst[2] = {0.f, 0.f};     // cells: (u = wr*4+qq2+2*(gt&1), col = wb*16+(gt>>1)*8+2*tg+j)
    __syncthreads();

    for (int t = 0; t < TT; t++) {
        int slot = t & 3;
        const __nv_bfloat16* hbi = g_hbhi[slot];
        const __nv_bfloat16* hbl = g_hblo[slot];

        float acc[3][2][4];                    // [hh/hl/lh][n8][4]
        // acc[0] initialized from xproj fragment (DRAM latency hides under flag wait)
#pragma unroll
        for (int n = 0; n < 2; n++)
#pragma unroll
            for (int e = 0; e < 2; e++) {
                int R = wr * 16 + (lane >> 2) + 8 * e;       // local row'
                int rg = (R & 3) * 512 + j0 + (R >> 2);      // global gate row
                int C = wb * 16 + n * 8 + 2 * tg;
                float2 v = __ldcg((const float2*)&g_xproj[(size_t)rg * MTOT
                                                          + (size_t)t * 128 + b0 + C]);
                acc[0][n][2 * e + 0] = v.x;
                acc[0][n][2 * e + 1] = v.y;
            }
#pragma unroll
        for (int a = 1; a < 3; a++)
#pragma unroll
            for (int n = 0; n < 2; n++)
#pragma unroll
                for (int q = 0; q < 4; q++) acc[a][n][q] = 0.f;

        // wavefront prologue: wait only producers of chunks 0,1 (rowg 0..15)
        if (t > 0) {
            if (tid < 16) {
                unsigned tgt = gbase + (unsigned)t;
                while ((int)(ld_acq(&g_pflag[bg][tid]) - tgt) < 0) {}
            }
            __syncthreads();
        }

        // prologue: chunks 0,1
        issue_chunk(ub + SB_BASE, hbi, hbl, b0, 0, tid);
        CP_COMMIT();
        issue_chunk(ub + SB_BASE + 16384, hbi, hbl, b0, 1, tid);
        CP_COMMIT();

        for (int kc = 0; kc < 4; kc++) {
            if (kc < 3) { CP_WAIT1(); } else { CP_WAIT0(); }
            __syncthreads();
            // poll next group's producers (warp0 lanes) while MMA runs below
            if (t > 0 && kc + 2 < 4 && tid < 8) {
                unsigned tgt = gbase + (unsigned)t;
                while ((int)(ld_acq(&g_pflag[bg][8 * (kc + 2) + tid]) - tgt) < 0) {}
            }
            uint32_t bb = ub + SB_BASE + (kc % 3) * 16384;
#pragma unroll
            for (int ktl = 0; ktl < 8; ktl++) {
                int ktg = kc * 8 + ktl;        // global k16 index 0..31
                uint32_t aoff = (uint32_t)(((wr * 2 + ((lane >> 3) & 1)) * 64
                                            + (2 * ktg + (lane >> 4))) * 128
                                           + (lane & 7) * 16);
                uint32_t boff = (uint32_t)(((wb * 2 + (lane >> 4)) * 16
                                            + (2 * ktl + ((lane >> 3) & 1))) * 128
                                           + (lane & 7) * 16);
                uint32_t ah[4], al[4], bh[4], bl[4];
                ldsm4(ah[0], ah[1], ah[2], ah[3], ub + SW_HI + aoff);
                ldsm4(bh[0], bh[1], bh[2], bh[3], bb + boff);
                ldsm4(al[0], al[1], al[2], al[3], ub + SW_LO + aoff);
                ldsm4(bl[0], bl[1], bl[2], bl[3], bb + 8192 + boff);
                mma16816(acc[0][0], ah, bh + 0);
                mma16816(acc[0][1], ah, bh + 2);
                mma16816(acc[1][0], ah, bl + 0);
                mma16816(acc[1][1], ah, bl + 2);
                mma16816(acc[2][0], al, bh + 0);
                mma16816(acc[2][1], al, bh + 2);
            }
            if (kc + 2 < 4) {
                __syncthreads();               // MMA on reused buffer done; flags passed
                issue_chunk(ub + SB_BASE + ((kc + 2) % 3) * 16384, hbi, hbl, b0, kc + 2, tid);
                CP_COMMIT();
            }
        }

        // ---- in-warp epilogue: no block syncs until staging complete ----
        // publish this lane's gate preacts into the warp slab, keyed so a
        // single LDS.128 returns {f,i,g,o} for one cell.
        {
            float* wx = (float*)(sm + SXC) + wid * 256;
#pragma unroll
            for (int n = 0; n < 2; n++)
#pragma unroll
                for (int e = 0; e < 2; e++)
#pragma unroll
                    for (int c = 0; c < 2; c++) {
                        int s = n * 4 + e * 2 + c;
                        wx[((qq2 * 8 + s) * 4 + tg) * 4 + gt] =
                            acc[0][n][2 * e + c] + acc[1][n][2 * e + c] + acc[2][n][2 * e + c];
                    }
            __syncwarp();
            int p = gt;                        // slot selector for this lane
#pragma unroll
            for (int j = 0; j < 2; j++) {
                int s = 2 * p + j;             // n = p>>1, e = p&1, c = j
                float4 v = *(const float4*)&wx[((qq2 * 8 + s) * 4 + tg) * 4];
                float fg = sigf(v.x), ig = sigf(v.y), gg = tanhf(v.z), og = sigf(v.w);
                float cn = fg * cst[j] + ig * gg;
                cst[j] = cn;
                float hv = og * tanhf(cn);
                int u = wr * 4 + qq2 + 2 * (p & 1);
                int col = wb * 16 + (p >> 1) * 8 + 2 * tg + j;
                sOut[col * 16 + u] = hv;
                __nv_bfloat16 hh = __float2bfloat16(hv);
                sHhi[col * 16 + u] = hh;
                sHlo[col * 16 + u] = __float2bfloat16(hv - __bfloat162float(hh));
                if (t == TT - 1) {
                    out[OUTBASE + (size_t)(b0 + col) * 512 + j0 + u] = hv;
                    out[OUTBASE + (size_t)BB * HD + (size_t)(b0 + col) * 512 + j0 + u] = cn;
                }
            }
        }
        __syncthreads();

        // h ring write (critical path) — coalesced from staging
        {
            int nslot = (t + 1) & 3;
            if (tid < 128) {
                int mat = tid >> 6;                // 0 hi, 1 lo
                int r = tid & 63;
                int b = r >> 1, half = r & 1;
                const __nv_bfloat16* s = mat ? sHlo : sHhi;
                float4 v = *(const float4*)&s[b * 16 + half * 8];
                __nv_bfloat16* dst = (mat ? g_hblo : g_hbhi)[nslot]
                                     + (size_t)(b0 + b) * 512 + j0 + half * 8;
                *(float4*)dst = v;
            }
        }
        __syncthreads();
        // release first — consumers proceed while we do the out DRAM write
        if (tid == 0) st_rel(&g_pflag[bg][rowg], gbase + (unsigned)t + 1u);

        // out write — off the inter-CTA critical path
        if (tid < 128) {
            int bb2 = tid >> 2, qc = tid & 3;
            float4 v = *(const float4*)&sOut[bb2 * 16 + qc * 4];
            *(float4*)&out[((size_t)t * 128 + b0 + bb2) * 512 + j0 + qc * 4] = v;
        }
        __syncthreads();
    }
}

extern "C" void kernel_launch(void* const* d_in, const int* in_sizes, int n_in,
                              void* d_out, int out_size) {
    const float* X  = (const float*)d_in[0];
    const float* Wf = (const float*)d_in[1];
    const float* bf = (const float*)d_in[2];
    const float* Wi = (const float*)d_in[3];
    const float* bi = (const float*)d_in[4];
    const float* Wg = (const float*)d_in[5];
    const float* bg = (const float*)d_in[6];
    const float* Wo = (const float*)d_in[7];
    const float* bo = (const float*)d_in[8];
    float* out = (float*)d_out;

    const int mma_smem = 4 * 16384 + 128;   // ~64.1KB
    cudaFuncSetAttribute(xproj_mma, cudaFuncAttributeMaxDynamicSharedMemorySize, mma_smem);
    cudaFuncSetAttribute(lstm_tc, cudaFuncAttributeMaxDynamicSharedMemorySize, SM_TOT);

    pack_kernel<<<(NR * DIN + 255) / 256, 256>>>(Wf, Wi, Wg, Wo, bf, bi, bg, bo);
    split_x<<<(int)(((size_t)MTOT * DIN / 4 + 255) / 256), 256>>>(X);
    dim3 ggrid(MTOT / 128, NR / 128);   // (512, 16)
    xproj_mma<<<ggrid, 256, mma_smem>>>(0);
    lstm_tc<<<128, 256, SM_TOT>>>(out);
}

// round 16
// speedup vs baseline: 1.1956x; 1.0325x over previous
#include <cuda_runtime.h>
#include <cuda_bf16.h>
#include <math.h>
#include <stdint.h>

#define TT 512
#define BB 128
#define DIN 512
#define HD 512
#define NR 2048
#define MTOT (TT * BB)          // 65536
#define OUTBASE ((size_t)TT * BB * HD)

// ---------------- scratch ----------------
__device__ __nv_bfloat16 g_Xhi[(size_t)MTOT * DIN];
__device__ __nv_bfloat16 g_Xlo[(size_t)MTOT * DIN];
__device__ __nv_bfloat16 g_Whi[NR * DIN];        // x-part weights hi
__device__ __nv_bfloat16 g_Wlo[NR * DIN];        // x-part weights lo
__device__ __nv_bfloat16 g_Rhi[NR * HD];         // h-part weights hi
__device__ __nv_bfloat16 g_Rlo[NR * HD];         // h-part weights lo
__device__ float g_bias[NR];
__device__ float g_xproj[(size_t)NR * MTOT];     // [r][m]
__device__ __nv_bfloat16 g_hbhi[4][BB * HD];     // h hi, [b][k], 4-slot ring
__device__ __nv_bfloat16 g_hblo[4][BB * HD];     // h lo
__device__ unsigned g_pflag[4][32][32];          // [bg][rowg][pad] - 1 flag per 128B line

// ---------------- PTX helpers (sm_80-compatible ISA only) ----------------
__device__ __forceinline__ uint32_t smem_u32(const void* p) {
    uint32_t a;
    asm("{ .reg .u64 t; cvta.to.shared.u64 t, %1; cvt.u32.u64 %0, t; }" : "=r"(a) : "l"(p));
    return a;
}

__device__ __forceinline__ void ldsm4(uint32_t& r0, uint32_t& r1, uint32_t& r2, uint32_t& r3,
                                      uint32_t addr) {
    asm volatile("ldmatrix.sync.aligned.m8n8.x4.shared.b16 {%0,%1,%2,%3}, [%4];"
                 : "=r"(r0), "=r"(r1), "=r"(r2), "=r"(r3) : "r"(addr));
}

__device__ __forceinline__ void mma16816(float* c, const uint32_t* a, const uint32_t* b) {
    asm volatile("mma.sync.aligned.m16n8k16.row.col.f32.bf16.bf16.f32 "
                 "{%0,%1,%2,%3}, {%4,%5,%6,%7}, {%8,%9}, {%0,%1,%2,%3};"
                 : "+f"(c[0]), "+f"(c[1]), "+f"(c[2]), "+f"(c[3])
                 : "r"(a[0]), "r"(a[1]), "r"(a[2]), "r"(a[3]), "r"(b[0]), "r"(b[1]));
}

__device__ __forceinline__ void cpasync16(uint32_t saddr, const void* g) {
    asm volatile("cp.async.cg.shared.global [%0], [%1], 16;" :: "r"(saddr), "l"(g));
}
#define CP_COMMIT() asm volatile("cp.async.commit_group;" ::: "memory")
#define CP_WAIT1()  asm volatile("cp.async.wait_group 1;" ::: "memory")
#define CP_WAIT0()  asm volatile("cp.async.wait_group 0;" ::: "memory")

__device__ __forceinline__ unsigned ld_acq(const unsigned* p) {
    unsigned v;
    asm volatile("ld.acquire.gpu.global.u32 %0, [%1];" : "=r"(v) : "l"(p) : "memory");
    return v;
}
__device__ __forceinline__ void st_rel(unsigned* p, unsigned v) {
    asm volatile("st.release.gpu.global.u32 [%0], %1;" :: "l"(p), "r"(v) : "memory");
}

// ---------------- pack weights (bf16 hi/lo both halves), zero h0 ----------------
__global__ void pack_kernel(const float* __restrict__ Wf, const float* __restrict__ Wi,
                            const float* __restrict__ Wg_, const float* __restrict__ Wo,
                            const float* __restrict__ bf, const float* __restrict__ bi,
                            const float* __restrict__ bg, const float* __restrict__ bo) {
    int idx = blockIdx.x * blockDim.x + threadIdx.x;
    if (idx < NR * DIN) {
        int r = idx >> 9;
        int k = idx & 511;
        int gate = r >> 9;
        int j = r & 511;
        const float* W = (gate == 0) ? Wf : (gate == 1) ? Wi : (gate == 2) ? Wg_ : Wo;
        float wx = W[j * 1024 + k];
        __nv_bfloat16 hi = __float2bfloat16(wx);
        g_Whi[idx] = hi;
        g_Wlo[idx] = __float2bfloat16(wx - __bfloat162float(hi));
        float wh = W[j * 1024 + 512 + k];
        __nv_bfloat16 rh = __float2bfloat16(wh);
        g_Rhi[idx] = rh;
        g_Rlo[idx] = __float2bfloat16(wh - __bfloat162float(rh));
        if (k == 0) {
            const float* bb = (gate == 0) ? bf : (gate == 1) ? bi : (gate == 2) ? bg : bo;
            g_bias[r] = bb[j];
        }
    }
    if (idx < BB * HD) {
        g_hbhi[0][idx] = __float2bfloat16(0.f);
        g_hblo[0][idx] = __float2bfloat16(0.f);
    }
}

// ---------------- split X into bf16 hi/lo ----------------
__global__ void split_x(const float* __restrict__ X) {
    size_t i = (size_t)blockIdx.x * blockDim.x + threadIdx.x;  // float4 index
    if (i < (size_t)MTOT * DIN / 4) {
        float4 v = __ldg((const float4*)X + i);
        __nv_bfloat16 h0 = __float2bfloat16(v.x), h1 = __float2bfloat16(v.y);
        __nv_bfloat16 h2 = __float2bfloat16(v.z), h3 = __float2bfloat16(v.w);
        __nv_bfloat162* ph = (__nv_bfloat162*)g_Xhi;
        __nv_bfloat162* pl = (__nv_bfloat162*)g_Xlo;
        ph[i * 2] = __nv_bfloat162(h0, h1);
        ph[i * 2 + 1] = __nv_bfloat162(h2, h3);
        pl[i * 2] = __nv_bfloat162(__float2bfloat16(v.x - __bfloat162float(h0)),
                                   __float2bfloat16(v.y - __bfloat162float(h1)));
        pl[i * 2 + 1] = __nv_bfloat162(__float2bfloat16(v.z - __bfloat162float(h2)),
                                       __float2bfloat16(v.w - __bfloat162float(h3)));
    }
}

// ---------------- xproj via mma.sync (proven in R8) ----------------
__global__ void __launch_bounds__(256) xproj_mma(int dummy) {
    extern __shared__ char smraw[];
    char* smp = (char*)(((uintptr_t)smraw + 127) & ~(uintptr_t)127);
    uint32_t ub = smem_u32(smp);
    int tid = threadIdx.x, wid = tid >> 5, lane = tid & 31;
    int wr = wid & 1, wm = wid >> 1;
    int r0 = blockIdx.y * 128, m0 = blockIdx.x * 128;

    float acc[4][4][4];
#pragma unroll
    for (int f = 0; f < 4; f++)
#pragma unroll
        for (int mf = 0; mf < 4; mf++)
#pragma unroll
            for (int q = 0; q < 4; q++) acc[f][mf][q] = 0.f;

    const __nv_bfloat16* srcs[4] = {
        g_Whi + (size_t)r0 * DIN, g_Wlo + (size_t)r0 * DIN,
        g_Xhi + (size_t)m0 * DIN, g_Xlo + (size_t)m0 * DIN };

    for (int kc = 0; kc < 8; kc++) {
        __syncthreads();
#pragma unroll
        for (int mat = 0; mat < 4; mat++) {
            const float4* src = (const float4*)srcs[mat];
            char* dst = smp + mat * 16384;
#pragma unroll
            for (int it = 0; it < 4; it++) {
                int idx = tid + it * 256;
                int row = idx & 127;
                int kt8 = idx >> 7;
                uint32_t off = (uint32_t)(((row >> 3) * 8 + kt8) * 128 + (row & 7) * 16);
                *(float4*)(dst + off) = __ldg(src + (size_t)row * 64 + kc * 8 + kt8);
            }
        }
        __syncthreads();
        uint32_t aH = ub, aL = ub + 16384, bH = ub + 32768, bL = ub + 49152;
#pragma unroll
        for (int kk = 0; kk < 4; kk++) {
            uint32_t aoff[4], boff[2];
#pragma unroll
            for (int f = 0; f < 4; f++)
                aoff[f] = (uint32_t)(((wr * 8 + f * 2 + ((lane >> 3) & 1)) * 8
                                      + (2 * kk + (lane >> 4))) * 128 + (lane & 7) * 16);
#pragma unroll
            for (int p = 0; p < 2; p++)
                boff[p] = (uint32_t)(((wm * 4 + 2 * p + (lane >> 4)) * 8
                                      + (2 * kk + ((lane >> 3) & 1))) * 128 + (lane & 7) * 16);

            uint32_t ah[4][4], bh[4][2];
#pragma unroll
            for (int f = 0; f < 4; f++)
                ldsm4(ah[f][0], ah[f][1], ah[f][2], ah[f][3], aH + aoff[f]);
#pragma unroll
            for (int p = 0; p < 2; p++)
                ldsm4(bh[2 * p][0], bh[2 * p][1], bh[2 * p + 1][0], bh[2 * p + 1][1],
                      bH + boff[p]);
#pragma unroll
            for (int f = 0; f < 4; f++)
#pragma unroll
                for (int mf = 0; mf < 4; mf++)
                    mma16816(acc[f][mf], ah[f], bh[mf]);
            {
                uint32_t bl[4][2];
#pragma unroll
                for (int p = 0; p < 2; p++)
                    ldsm4(bl[2 * p][0], bl[2 * p][1], bl[2 * p + 1][0], bl[2 * p + 1][1],
                          bL + boff[p]);
#pragma unroll
                for (int f = 0; f < 4; f++)
#pragma unroll
                    for (int mf = 0; mf < 4; mf++)
                        mma16816(acc[f][mf], ah[f], bl[mf]);
            }
            {
#pragma unroll
                for (int f = 0; f < 4; f++) {
                    uint32_t av[4];
                    ldsm4(av[0], av[1], av[2], av[3], aL + aoff[f]);
#pragma unroll
                    for (int mf = 0; mf < 4; mf++)
                        mma16816(acc[f][mf], av, bh[mf]);
                }
            }
        }
    }
    int g = lane >> 2, t2 = (lane & 3) * 2;
#pragma unroll
    for (int f = 0; f < 4; f++) {
        int r = r0 + wr * 64 + f * 16 + g;
        float b0 = __ldg(&g_bias[r]);
        float b1 = __ldg(&g_bias[r + 8]);
#pragma unroll
        for (int mf = 0; mf < 4; mf++) {
            int m = m0 + wm * 32 + mf * 8 + t2;
            float2 v0 = make_float2(acc[f][mf][0] + b0, acc[f][mf][1] + b0);
            float2 v1 = make_float2(acc[f][mf][2] + b1, acc[f][mf][3] + b1);
            *(float2*)&g_xproj[(size_t)r * MTOT + m] = v0;
            *(float2*)&g_xproj[(size_t)(r + 8) * MTOT + m] = v1;
        }
    }
}

// ---------------- persistent tensor-core LSTM recurrence ----------------
__device__ __forceinline__ float sigf(float x) { return 1.f / (1.f + expf(-x)); }

// smem byte offsets (dynamic). Per CTA: 64 rows (16 units x 4 gates) x 32 batches.
// Local row ordering: row' = unit*4 + gate  (gate quartet warp-local)
#define SW_HI   0          // W hi: 64r x 512k tiled                               (64KB)
#define SW_LO   65536      // W lo                                                 (64KB)
#define SB_BASE 131072     // h chunks: 2 bufs x 32KB (hi 16KB + lo 16KB)          (64KB)
#define SXC     196608     // warp-exchange: 8 warps x 1KB                          (8KB)
#define SH_HI   204800     // bf16[32][16] h-out staging hi                          (1KB)
#define SH_LO   205824     // bf16[32][16] lo                                        (1KB)
#define SOUT    206848     // float[32][16] out staging                              (2KB)
#define SM_TOT  208896

// chunk kc in {0,1}: k in [kc*256, kc*256+256), batches b0..b0+31, hi+lo (32KB)
// per-matrix tile (bt = bl>>3, kt8 0..31): soff = (bt*32+kt8)*128 + (bl&7)*16
__device__ __forceinline__ void issue_chunk2(uint32_t sbuf, const __nv_bfloat16* hbi,
                                             const __nv_bfloat16* hbl, int b0, int kc, int tid) {
#pragma unroll
    for (int q = 0; q < 8; q++) {
        int idx = q * 256 + tid;               // 0..2047
        int mat = idx >> 10;                   // 0 hi, 1 lo
        int r = idx & 1023;
        int bl = r >> 5, seg = r & 31;         // seg = local kt8
        uint32_t soff = (uint32_t)((((bl >> 3) * 32 + seg) * 128 + (bl & 7) * 16)
                                   + mat * 16384);
        const __nv_bfloat16* src = mat ? hbl : hbi;
        cpasync16(sbuf + soff, src + (size_t)(b0 + bl) * 512 + kc * 256 + seg * 8);
    }
}

// grid 128 CTAs (32 row-groups x 4 batch-groups) x 256 threads.
__global__ void __launch_bounds__(256, 1) lstm_tc(float* __restrict__ out) {
    extern __shared__ char sm[];
    uint32_t ub = smem_u32(sm);
    __nv_bfloat16* sHhi = (__nv_bfloat16*)(sm + SH_HI);
    __nv_bfloat16* sHlo = (__nv_bfloat16*)(sm + SH_LO);
    float* sOut = (float*)(sm + SOUT);
    int tid = threadIdx.x, wid = tid >> 5, lane = tid & 31;
    int wr = wid & 3;              // m-tile: units wr*4..wr*4+3 (x4 gates = 16 rows)
    int wb = wid >> 2;             // n-half (16 batches)
    int rowg = blockIdx.x >> 2, bg = blockIdx.x & 3;
    int j0 = rowg * 16;            // units j0..j0+15
    int b0 = bg * 32;              // batches b0..b0+31
    int qq2 = lane >> 4;           // unit-quad half (0,1)
    int gt = (lane >> 2) & 3;      // gate owned by this lane's A-fragment rows
    int tg = lane & 3;

    // replay-safe monotonic generation base (only this CTA writes its word)
    unsigned gbase = *(volatile unsigned*)&g_pflag[bg][rowg][0];

    // tile W hi/lo into smem once: 64 rows x 512 k, 8x8-b16 tiles
    // local row lr = unit*4 + gate  ->  global gate row = gate*512 + j0 + unit
#pragma unroll
    for (int q = 0; q < 32; q++) {
        int idx = q * 256 + tid;               // 0..8191
        int mat = idx >> 12;                   // 0 hi, 1 lo
        int r2 = idx & 4095;
        int lr = r2 >> 6, kseg = r2 & 63;
        int rg = (lr & 3) * 512 + j0 + (lr >> 2);
        uint32_t soff = (uint32_t)((((lr >> 3) * 64 + kseg) * 128 + (lr & 7) * 16)
                                   + mat * 65536);
        const __nv_bfloat16* src = mat ? g_Rlo : g_Rhi;
        *(float4*)(sm + soff) = __ldg((const float4*)(src + (size_t)rg * 512 + kseg * 8));
    }

    float cst[2] = {0.f, 0.f};
    __syncthreads();

    for (int t = 0; t < TT; t++) {
        int slot = t & 3;
        const __nv_bfloat16* hbi = g_hbhi[slot];
        const __nv_bfloat16* hbl = g_hblo[slot];
        unsigned tgt = gbase + (unsigned)t;

        float acc[3][2][4];                    // [hh/hl/lh][n8][4]
        // acc[0] initialized from xproj fragment (DRAM latency hides under polls)
#pragma unroll
        for (int n = 0; n < 2; n++)
#pragma unroll
            for (int e = 0; e < 2; e++) {
                int R = wr * 16 + (lane >> 2) + 8 * e;       // local row'
                int rg = (R & 3) * 512 + j0 + (R >> 2);      // global gate row
                int C = wb * 16 + n * 8 + 2 * tg;
                float2 v = __ldcg((const float2*)&g_xproj[(size_t)rg * MTOT
                                                          + (size_t)t * 128 + b0 + C]);
                acc[0][n][2 * e + 0] = v.x;
                acc[0][n][2 * e + 1] = v.y;
            }
#pragma unroll
        for (int a = 1; a < 3; a++)
#pragma unroll
            for (int n = 0; n < 2; n++)
#pragma unroll
                for (int q = 0; q < 4; q++) acc[a][n][q] = 0.f;

        // per-warp gate on producers of chunk 0 (rowg 0..15), then issue
        if (t > 0 && lane < 16) {
            while ((int)(ld_acq(&g_pflag[bg][lane][0]) - tgt) < 0) {}
        }
        __syncwarp();
        issue_chunk2(ub + SB_BASE, hbi, hbl, b0, 0, tid);
        CP_COMMIT();

        // per-warp gate on producers of chunk 1 (rowg 16..31) — overlaps chunk0 flight
        if (t > 0 && lane < 16) {
            while ((int)(ld_acq(&g_pflag[bg][16 + lane][0]) - tgt) < 0) {}
        }
        __syncwarp();
        issue_chunk2(ub + SB_BASE + 32768, hbi, hbl, b0, 1, tid);
        CP_COMMIT();

        // ---- MMA over 2 chunks: 2 sync points total ----
#pragma unroll
        for (int kc = 0; kc < 2; kc++) {
            if (kc == 0) { CP_WAIT1(); } else { CP_WAIT0(); }
            __syncthreads();
            uint32_t bb = ub + SB_BASE + kc * 32768;
#pragma unroll
            for (int ktl = 0; ktl < 16; ktl++) {
                int ktg = kc * 16 + ktl;       // global k16 index 0..31
                uint32_t aoff = (uint32_t)(((wr * 2 + ((lane >> 3) & 1)) * 64
                                            + (2 * ktg + (lane >> 4))) * 128
                                           + (lane & 7) * 16);
                uint32_t boff = (uint32_t)(((wb * 2 + (lane >> 4)) * 32
                                            + (2 * ktl + ((lane >> 3) & 1))) * 128
                                           + (lane & 7) * 16);
                uint32_t ah[4], al[4], bh[4], bl[4];
                ldsm4(ah[0], ah[1], ah[2], ah[3], ub + SW_HI + aoff);
                ldsm4(bh[0], bh[1], bh[2], bh[3], bb + boff);
                ldsm4(al[0], al[1], al[2], al[3], ub + SW_LO + aoff);
                ldsm4(bl[0], bl[1], bl[2], bl[3], bb + 16384 + boff);
                mma16816(acc[0][0], ah, bh + 0);
                mma16816(acc[0][1], ah, bh + 2);
                mma16816(acc[1][0], ah, bl + 0);
                mma16816(acc[1][1], ah, bl + 2);
                mma16816(acc[2][0], al, bh + 0);
                mma16816(acc[2][1], al, bh + 2);
            }
        }

        // ---- in-warp epilogue ----
        {
            float* wx = (float*)(sm + SXC) + wid * 256;
#pragma unroll
            for (int n = 0; n < 2; n++)
#pragma unroll
                for (int e = 0; e < 2; e++)
#pragma unroll
                    for (int c = 0; c < 2; c++) {
                        int s = n * 4 + e * 2 + c;
                        wx[((qq2 * 8 + s) * 4 + tg) * 4 + gt] =
                            acc[0][n][2 * e + c] + acc[1][n][2 * e + c] + acc[2][n][2 * e + c];
                    }
            __syncwarp();
            int p = gt;
#pragma unroll
            for (int j = 0; j < 2; j++) {
                int s = 2 * p + j;
                float4 v = *(const float4*)&wx[((qq2 * 8 + s) * 4 + tg) * 4];
                float fg = sigf(v.x), ig = sigf(v.y), gg = tanhf(v.z), og = sigf(v.w);
                float cn = fg * cst[j] + ig * gg;
                cst[j] = cn;
                float hv = og * tanhf(cn);
                int u = wr * 4 + qq2 + 2 * (p & 1);
                int col = wb * 16 + (p >> 1) * 8 + 2 * tg + j;
                sOut[col * 16 + u] = hv;
                __nv_bfloat16 hh = __float2bfloat16(hv);
                sHhi[col * 16 + u] = hh;
                sHlo[col * 16 + u] = __float2bfloat16(hv - __bfloat162float(hh));
                if (t == TT - 1) {
                    out[OUTBASE + (size_t)(b0 + col) * 512 + j0 + u] = hv;
                    out[OUTBASE + (size_t)BB * HD + (size_t)(b0 + col) * 512 + j0 + u] = cn;
                }
            }
        }
        __syncthreads();

        // h ring write (critical path) — coalesced from staging
        {
            int nslot = (t + 1) & 3;
            if (tid < 128) {
                int mat = tid >> 6;                // 0 hi, 1 lo
                int r = tid & 63;
                int b = r >> 1, half = r & 1;
                const __nv_bfloat16* s = mat ? sHlo : sHhi;
                float4 v = *(const float4*)&s[b * 16 + half * 8];
                __nv_bfloat16* dst = (mat ? g_hblo : g_hbhi)[nslot]
                                     + (size_t)(b0 + b) * 512 + j0 + half * 8;
                *(float4*)dst = v;
            }
        }
        __syncthreads();
        // release first — consumers proceed while we do the out DRAM write
        if (tid == 0) st_rel(&g_pflag[bg][rowg][0], gbase + (unsigned)t + 1u);

        // out write — off the inter-CTA critical path
        if (tid < 128) {
            int bb2 = tid >> 2, qc = tid & 3;
            float4 v = *(const float4*)&sOut[bb2 * 16 + qc * 4];
            *(float4*)&out[((size_t)t * 128 + b0 + bb2) * 512 + j0 + qc * 4] = v;
        }
        __syncthreads();
    }
}

extern "C" void kernel_launch(void* const* d_in, const int* in_sizes, int n_in,
                              void* d_out, int out_size) {
    const float* X  = (const float*)d_in[0];
    const float* Wf = (const float*)d_in[1];
    const float* bf = (const float*)d_in[2];
    const float* Wi = (const float*)d_in[3];
    const float* bi = (const float*)d_in[4];
    const float* Wg = (const float*)d_in[5];
    const float* bg = (const float*)d_in[6];
    const float* Wo = (const float*)d_in[7];
    const float* bo = (const float*)d_in[8];
    float* out = (float*)d_out;

    const int mma_smem = 4 * 16384 + 128;   // ~64.1KB
    cudaFuncSetAttribute(xproj_mma, cudaFuncAttributeMaxDynamicSharedMemorySize, mma_smem);
    cudaFuncSetAttribute(lstm_tc, cudaFuncAttributeMaxDynamicSharedMemorySize, SM_TOT);

    pack_kernel<<<(NR * DIN + 255) / 256, 256>>>(Wf, Wi, Wg, Wo, bf, bi, bg, bo);
    split_x<<<(int)(((size_t)MTOT * DIN / 4 + 255) / 256), 256>>>(X);
    dim3 ggrid(MTOT / 128, NR / 128);   // (512, 16)
    xproj_mma<<<ggrid, 256, mma_smem>>>(0);
    lstm_tc<<<128, 256, SM_TOT>>>(out);
}